// round 11
// baseline (speedup 1.0000x reference)
#include <cuda_runtime.h>
#include <cuda_fp16.h>
#include <cstdint>

#define EPSBN 1e-3f
#define WPITCH 132
#define WWORDS (16 * WPITCH)         // 2112 words (k16 chunk of W)
#define NBUF 4                       // 4 buffers, 3 chunks in flight

// fp16 intermediate y
__device__ __half g_yh[64 * 512 * 128];

__device__ __forceinline__ uint32_t s2u(const void* p) {
    uint32_t a;
    asm("{ .reg .u64 t; cvta.to.shared.u64 t, %1; cvt.u32.u64 %0, t; }" : "=r"(a) : "l"(p));
    return a;
}
__device__ __forceinline__ void cpa16(uint32_t d, const void* s, uint32_t sz) {
    asm volatile("cp.async.cg.shared.global [%0], [%1], 16, %2;"
                 :: "r"(d), "l"(s), "r"(sz) : "memory");
}
__device__ __forceinline__ void cpa16_ef(uint32_t d, const void* s) {
    asm volatile(
        "{\n\t.reg .b64 pol;\n\t"
        "createpolicy.fractional.L2::evict_first.b64 pol, 1.0;\n\t"
        "cp.async.cg.shared.global.L2::cache_hint [%0], [%1], 16, pol;\n\t}"
        :: "r"(d), "l"(s) : "memory");
}
__device__ __forceinline__ void l2pf(const void* p) {
    asm volatile("prefetch.global.L2 [%0];" :: "l"(p));
}
__device__ __forceinline__ void cpcommit() { asm volatile("cp.async.commit_group;" ::: "memory"); }
template <int N> __device__ __forceinline__ void cpwait() {
    asm volatile("cp.async.wait_group %0;" :: "n"(N) : "memory");
}
__device__ __forceinline__ uint32_t packh2(float lo, float hi) {
    __half2 h = __floats2half2_rn(lo, hi);
    return *(uint32_t*)&h;
}
__device__ __forceinline__ void mma16(float* d, const uint32_t* a, const uint32_t* b) {
    asm volatile(
        "mma.sync.aligned.m16n8k16.row.col.f32.f16.f16.f32 "
        "{%0,%1,%2,%3}, {%4,%5,%6,%7}, {%8,%9}, {%0,%1,%2,%3};"
        : "+f"(d[0]), "+f"(d[1]), "+f"(d[2]), "+f"(d[3])
        : "r"(a[0]), "r"(a[1]), "r"(a[2]), "r"(a[3]), "r"(b[0]), "r"(b[1]));
}

// ============================================================================
// GEMM core: D[MTILE m, 128 f] = A[MTILE, K] * half(W)[K, 128], fp32 accum.
// THREADS = 2*MTILE. MTILE=64: 4 warps, warp wi owns f-slice wi*32 (nt=4).
// MTILE=128: 8 warps; wg=wid>>2 picks row-half (wg*64), wi=wid&3 the f-slice.
// k16 chunks, NBUF=4 ring, 3 chunks in flight, tail-correct waits.
// AFP32: A staged from fp32 src via predicated ld+cvt+sts (index in
//        [0,32768) else zero -- conv SAME padding). Else: fp16 src, cp.async.
// EF: evict_first policy + deep (c+8) L2 prefetch on the streaming W.
// ============================================================================
template <int NC, int MTILE, bool AFP32, bool EF, typename AT>
__device__ __forceinline__ void gemm_core(
    uint32_t* As, const float* __restrict__ W, const AT* __restrict__ Ah,
    int off0, int mstride, float acc[4][4][4], int tid) {
    constexpr int THREADS = MTILE * 2;
    constexpr int AW = MTILE * 12;       // A words per buffer (pitch 12)
    constexpr int BW = AW + WWORDS;      // buffer words
    constexpr int WQ = 512 / THREADS;    // W float4 loads per thread (16x128 fp32)
    const int wid = tid >> 5, lane = tid & 31;
    const int wg = (MTILE == 128) ? (wid >> 2) : 0;
    const int wi = (MTILE == 128) ? (wid & 3) : wid;
    const int gp = lane >> 2, tg = lane & 3;
    const uint32_t smb = s2u(As);

    auto stage = [&](int c) {
        const int kc = c * 16;
        const uint32_t bb = smb + (uint32_t)((c & (NBUF - 1)) * BW) * 4u;
        if (AFP32) {
            // A: MTILE rows x 16 k fp32 -> 2 float4 loads/thread, cvt, sts
#pragma unroll
            for (int q = 0; q < 2; q++) {
                const int idx = tid + THREADS * q;
                const int m = idx >> 2, j4 = idx & 3;
                const int e = off0 + m * mstride + kc + j4 * 4;
                float4 v = make_float4(0.f, 0.f, 0.f, 0.f);
                if ((unsigned)e < 32768u) v = *(const float4*)((const float*)Ah + e);
                asm volatile("st.shared.v2.b32 [%0], {%1,%2};"
                             :: "r"(bb + (uint32_t)(m * 12 + j4 * 2) * 4u),
                                "r"(packh2(v.x, v.y)), "r"(packh2(v.z, v.w)) : "memory");
            }
        } else {
            // A: MTILE rows x 16 k fp16 -> 1 cpa16/thread
            const int m = tid >> 1, h = tid & 1;
            const int so = off0 + m * mstride + kc + h * 8;
            cpa16(bb + (uint32_t)(m * 12 + h * 4) * 4u, (const char*)Ah + (size_t)so * 2, 16u);
        }
        // W: 16 rows x 128 fp32 = 8KB
        const uint32_t wb = bb + (uint32_t)AW * 4u;
#pragma unroll
        for (int q = 0; q < WQ; q++) {
            const int idx = tid + THREADS * q;
            const int row = idx >> 5, c4 = idx & 31;
            const uint32_t d = wb + (uint32_t)(row * WPITCH + c4 * 4) * 4u;
            const float* s = W + (size_t)(kc + row) * 128 + c4 * 4;
            if (EF) cpa16_ef(d, s); else cpa16(d, s, 16u);
        }
        // Deep L2 prefetch: pull chunk c+8 DRAM->L2 now (64 lines of 128B)
        if (EF) {
            const int cf = c + 8;
            if (cf < NC && tid < 64)
                l2pf(W + (size_t)(cf * 16 + (tid >> 2)) * 128 + (tid & 3) * 32);
        }
        cpcommit();
    };

    stage(0); stage(1); stage(2);
    for (int c = 0; c < NC; c++) {
        if (c + 3 < NC)       { stage(c + 3); cpwait<3>(); }
        else if (c + 3 == NC) { cpwait<2>(); }
        else if (c + 2 == NC) { cpwait<1>(); }
        else                  { cpwait<0>(); }
        __syncthreads();
        const uint32_t* __restrict__ smA = As + (c & (NBUF - 1)) * BW;
        const float* __restrict__ smW = (const float*)(smA + AW);
        const int wcol = wi * 32 + gp;
        const float* wp = smW + tg * 2 * WPITCH + wcol;
        uint32_t b[8];
#pragma unroll
        for (int nt = 0; nt < 4; nt++) {
            b[2 * nt]     = packh2(wp[nt * 8], wp[WPITCH + nt * 8]);
            b[2 * nt + 1] = packh2(wp[8 * WPITCH + nt * 8], wp[9 * WPITCH + nt * 8]);
        }
#pragma unroll
        for (int mt = 0; mt < 4; mt++) {
            const int r = wg * 64 + mt * 16 + gp;
            uint32_t a[4];
            a[0] = smA[r * 12 + tg];
            a[1] = smA[(r + 8) * 12 + tg];
            a[2] = smA[r * 12 + tg + 4];
            a[3] = smA[(r + 8) * 12 + tg + 4];
#pragma unroll
            for (int nt = 0; nt < 4; nt++) mma16(acc[mt][nt], a, b + 2 * nt);
        }
        __syncthreads();
    }
}

// ---------------- Stage 1: Conv1D(SAME) + BN1 + ReLU -> g_yh ----------------
// M=128 l-tile, 256 threads / 8 warps, 58 KB dynamic smem, 2 blocks/SM.
__global__ __launch_bounds__(256, 2) void conv_tc(
    const float* __restrict__ x, const float* __restrict__ w,
    const float* __restrict__ cb,
    const float* __restrict__ g1, const float* __restrict__ b1,
    const float* __restrict__ m1, const float* __restrict__ v1) {
    extern __shared__ uint32_t As[];
    const int tid = threadIdx.x;
    const int b = blockIdx.y, l0 = blockIdx.x * 128;
    float acc[4][4][4] = {};
    gemm_core<28, 128, true, false>(As, w, x + (size_t)b * 32768, (l0 - 3) * 64, 64, acc, tid);
    const int wid = tid >> 5, lane = tid & 31, gp = lane >> 2, tg = lane & 3;
    const int wg = wid >> 2, wi = wid & 3;
#pragma unroll
    for (int nt = 0; nt < 4; nt++) {
        const int f = wi * 32 + nt * 8 + tg * 2;
        const float s0 = g1[f] * rsqrtf(v1[f] + EPSBN);
        const float s1 = g1[f + 1] * rsqrtf(v1[f + 1] + EPSBN);
        const float h0 = (cb[f] - m1[f]) * s0 + b1[f];
        const float h1 = (cb[f + 1] - m1[f + 1]) * s1 + b1[f + 1];
#pragma unroll
        for (int mt = 0; mt < 4; mt++) {
#pragma unroll
            for (int hr = 0; hr < 2; hr++) {
                const int l = l0 + wg * 64 + mt * 16 + gp + hr * 8;
                const float y0 = fmaxf(fmaf(acc[mt][nt][hr * 2], s0, h0), 0.f);
                const float y1 = fmaxf(fmaf(acc[mt][nt][hr * 2 + 1], s1, h1), 0.f);
                *(uint32_t*)&g_yh[(size_t)b * 65536 + (size_t)l * 128 + f] = packh2(y0, y1);
            }
        }
    }
}

// ---------------- Stage 2: LocallyConnected1D(VALID) + BN2 + ReLU ----------------
__global__ __launch_bounds__(128, 4) void local_tc(
    const float* __restrict__ lw, const float* __restrict__ lb,
    const float* __restrict__ g2, const float* __restrict__ b2,
    const float* __restrict__ m2, const float* __restrict__ v2,
    float* __restrict__ out) {
    extern __shared__ uint32_t As[];
    const int tid = threadIdx.x;
    const int l = blockIdx.x;
    float acc[4][4][4] = {};
    gemm_core<56, 64, false, true>(As, lw + (size_t)l * 896 * 128, g_yh, l * 128, 65536, acc, tid);
    const int wid = tid >> 5, lane = tid & 31, gp = lane >> 2, tg = lane & 3;
#pragma unroll
    for (int nt = 0; nt < 4; nt++) {
        const int f = wid * 32 + nt * 8 + tg * 2;
        const float s0 = g2[f] * rsqrtf(v2[f] + EPSBN);
        const float s1 = g2[f + 1] * rsqrtf(v2[f + 1] + EPSBN);
        const float h0 = (lb[l * 128 + f] - m2[f]) * s0 + b2[f];
        const float h1 = (lb[l * 128 + f + 1] - m2[f + 1]) * s1 + b2[f + 1];
#pragma unroll
        for (int mt = 0; mt < 4; mt++) {
#pragma unroll
            for (int hr = 0; hr < 2; hr++) {
                const int bat = mt * 16 + gp + hr * 8;
                float2 r;
                r.x = fmaxf(fmaf(acc[mt][nt][hr * 2], s0, h0), 0.f);
                r.y = fmaxf(fmaf(acc[mt][nt][hr * 2 + 1], s1, h1), 0.f);
                *(float2*)&out[(size_t)bat * 506 * 128 + (size_t)l * 128 + f] = r;
            }
        }
    }
}

#define CONV_SMEM (NBUF * (128 * 12 + WWORDS) * 4)   // 58368 B
#define LOCAL_SMEM (NBUF * (64 * 12 + WWORDS) * 4)   // 46080 B

extern "C" void kernel_launch(void* const* d_in, const int* in_sizes, int n_in,
                              void* d_out, int out_size) {
    const float* x      = (const float*)d_in[0];
    const float* conv_w = (const float*)d_in[1];
    const float* conv_b = (const float*)d_in[2];
    const float* g1     = (const float*)d_in[3];
    const float* b1     = (const float*)d_in[4];
    const float* m1     = (const float*)d_in[5];
    const float* v1     = (const float*)d_in[6];
    const float* lw     = (const float*)d_in[7];
    const float* lb     = (const float*)d_in[8];
    const float* g2     = (const float*)d_in[9];
    const float* b2     = (const float*)d_in[10];
    const float* m2     = (const float*)d_in[11];
    const float* v2     = (const float*)d_in[12];
    float* out = (float*)d_out;

    // Host-side attribute set (idempotent, capture-safe)
    cudaFuncSetAttribute(conv_tc, cudaFuncAttributeMaxDynamicSharedMemorySize, CONV_SMEM);

    conv_tc<<<dim3(4, 64), 256, CONV_SMEM>>>(x, conv_w, conv_b, g1, b1, m1, v1);
    local_tc<<<506, 128, LOCAL_SMEM>>>(lw, lb, g2, b2, m2, v2, out);
}